// round 14
// baseline (speedup 1.0000x reference)
#include <cuda_runtime.h>
#include <cuda_fp16.h>
#include <mma.h>
#include <cstdint>

using namespace nvcuda;

#define NNODES 50000
#define NEDGES 600000
#define NREL   8
#define NBASIS 32
#define RN     (NREL * NNODES)
#define SCAN_B 1024
#define NSCAN  ((RN + SCAN_B - 1) / SCAN_B)
#define NK     1152
#define MT     ((NNODES + 127) / 128)    // 391
#define MPAD   (MT * 128)                // 50048
#define KZ     3
#define KCH    12                         // 3 * 12 * 32 = 1152

// ---------------- static device scratch ----------------
static __device__ __align__(16) __half d_xh[(size_t)NNODES * 128];
static __device__ __align__(16) __half d_Ah[(size_t)NNODES * NK];
static __device__ __align__(16) __half d_Bh[128 * NK];
static __device__ __align__(16) __half d_Ch[512 * 128];
static __device__ __align__(16) float d_bcat[512];
static __device__ __align__(16) __half d_hh[(size_t)NNODES * 128];
static __device__ __align__(16) float d_P[KZ * (size_t)MPAD * 128];
static __device__ __align__(16) float d_kskip[(size_t)NNODES * 256];
static __device__ __align__(16) __half d_qvh[(size_t)NNODES * 256];
static __device__ int d_cnt[RN];
static __device__ int d_off[RN + 1];
static __device__ int d_cur[RN];
static __device__ int d_ssrc[NEDGES];
static __device__ int d_part[SCAN_B];
static __device__ int d_ppre[SCAN_B];

// ---------------- helpers ----------------
__device__ __forceinline__ float sigf(float z) { return 1.0f / (1.0f + __expf(-z)); }
__device__ __forceinline__ uint32_t smem_u32(const void* p) {
    uint32_t a;
    asm("{ .reg .u64 t; cvta.to.shared.u64 t, %1; cvt.u32.u64 %0, t; }" : "=r"(a) : "l"(p));
    return a;
}
__device__ __forceinline__ void cpa(uint32_t d, const void* s, int srcsz) {
    asm volatile("cp.async.cg.shared.global [%0], [%1], 16, %2;"
                 :: "r"(d), "l"(s), "r"(srcsz) : "memory");
}
#define CP_COMMIT() asm volatile("cp.async.commit_group;" ::: "memory")
#define CP_WAIT2()  asm volatile("cp.async.wait_group 2;" ::: "memory")
#define CP_WAIT0()  asm volatile("cp.async.wait_group 0;" ::: "memory")

// ---------------- x -> fp16, zero d_cnt ----------------
__global__ void convert_xh(const float* __restrict__ x) {
    int idx = blockIdx.x * blockDim.x + threadIdx.x;
    if (idx < RN) d_cnt[idx] = 0;
    if (idx >= NNODES * 32) return;
    float4 v = reinterpret_cast<const float4*>(x)[idx];
    __align__(8) __half hv[4];
    hv[0] = __float2half(v.x); hv[1] = __float2half(v.y);
    hv[2] = __float2half(v.z); hv[3] = __float2half(v.w);
    *(uint2*)&d_xh[(size_t)idx * 4] = *(uint2*)hv;
}

// ---------------- fused weight prep ----------------
__global__ void prep_weights(const float* __restrict__ comp, const float* __restrict__ basis,
                             const float* __restrict__ root,
                             const float* wk, const float* bk, const float* wq, const float* bq,
                             const float* wv, const float* bv, const float* ws, const float* bs) {
    int idx = blockIdx.x * blockDim.x + threadIdx.x;
    if (idx < 128 * NK) {
        int n = idx / NK, k = idx % NK;
        float w;
        if (k < 1024) {
            int r = k >> 7, i = k & 127;
            float s = 0.0f;
            #pragma unroll
            for (int b = 0; b < NBASIS; b++)
                s += comp[r * NBASIS + b] * basis[(b * 128 + i) * 128 + n];
            w = s;
        } else {
            w = root[(k - 1024) * 128 + n];
        }
        d_Bh[idx] = __float2half(w);
        return;
    }
    int j = idx - 128 * NK;
    if (j >= 512 * 128) return;
    int n = j >> 7, k = j & 127;
    int sel = n >> 7, cc = n & 127;
    const float* W = (sel == 0) ? wk : (sel == 1) ? wq : (sel == 2) ? wv : ws;
    d_Ch[j] = __float2half(W[k * 128 + cc]);
    if (k == 0) {
        const float* B = (sel == 0) ? bk : (sel == 1) ? bq : (sel == 2) ? bv : bs;
        d_bcat[n] = B[cc];
    }
}

// ---------------- CSR build ----------------
__global__ void count_edges(const int* __restrict__ ei, const int* __restrict__ etype) {
    int e = blockIdx.x * blockDim.x + threadIdx.x;
    if (e >= NEDGES) return;
    atomicAdd(&d_cnt[ei[NEDGES + e] * NREL + etype[e]], 1);
}

// warp-shuffle block sum
__global__ void scan_blocksum() {
    int tid = threadIdx.x, gid = blockIdx.x * SCAN_B + tid;
    int lane = tid & 31, wid = tid >> 5;
    int v = (gid < RN) ? d_cnt[gid] : 0;
    #pragma unroll
    for (int o = 16; o > 0; o >>= 1) v += __shfl_down_sync(0xFFFFFFFFu, v, o);
    __shared__ int ws[32];
    if (lane == 0) ws[wid] = v;
    __syncthreads();
    if (wid == 0) {
        int t = ws[lane];
        #pragma unroll
        for (int o = 16; o > 0; o >>= 1) t += __shfl_down_sync(0xFFFFFFFFu, t, o);
        if (lane == 0) d_part[blockIdx.x] = t;
    }
}

// warp-shuffle inclusive scan of 1024 -> exclusive prefix of block sums
__global__ void scan_partials() {
    int tid = threadIdx.x, lane = tid & 31, wid = tid >> 5;
    int v = (tid < NSCAN) ? d_part[tid] : 0;
    int x = v;
    #pragma unroll
    for (int o = 1; o < 32; o <<= 1) {
        int t = __shfl_up_sync(0xFFFFFFFFu, x, o);
        if (lane >= o) x += t;
    }
    __shared__ int ws[32];
    if (lane == 31) ws[wid] = x;
    __syncthreads();
    if (wid == 0) {
        int t = ws[lane];
        #pragma unroll
        for (int o = 1; o < 32; o <<= 1) {
            int u = __shfl_up_sync(0xFFFFFFFFu, t, o);
            if (lane >= o) t += u;
        }
        ws[lane] = t;
    }
    __syncthreads();
    int base = (wid > 0) ? ws[wid - 1] : 0;
    d_ppre[tid] = base + x - v;
}

// warp-shuffle block scan + global offset
__global__ void scan_final() {
    int tid = threadIdx.x, gid = blockIdx.x * SCAN_B + tid;
    int lane = tid & 31, wid = tid >> 5;
    int v = (gid < RN) ? d_cnt[gid] : 0;
    int x = v;
    #pragma unroll
    for (int o = 1; o < 32; o <<= 1) {
        int t = __shfl_up_sync(0xFFFFFFFFu, x, o);
        if (lane >= o) x += t;
    }
    __shared__ int ws[32];
    if (lane == 31) ws[wid] = x;
    __syncthreads();
    if (wid == 0) {
        int t = ws[lane];
        #pragma unroll
        for (int o = 1; o < 32; o <<= 1) {
            int u = __shfl_up_sync(0xFFFFFFFFu, t, o);
            if (lane >= o) t += u;
        }
        ws[lane] = t;
    }
    __syncthreads();
    int base = (wid > 0) ? ws[wid - 1] : 0;
    int ex = base + x - v + d_ppre[blockIdx.x];
    if (gid < RN) {
        d_off[gid] = ex; d_cur[gid] = ex;
        if (gid == RN - 1) d_off[RN] = ex + v;
    }
}

__global__ void scatter_edges(const int* __restrict__ ei, const int* __restrict__ etype) {
    int e = blockIdx.x * blockDim.x + threadIdx.x;
    if (e >= NEDGES) return;
    int pos = atomicAdd(&d_cur[ei[NEDGES + e] * NREL + etype[e]], 1);
    d_ssrc[pos] = ei[e];
}

// ---------------- gather + root copy, single launch ----------------
#define AGG_SEG_BLK (RN / 16)                 // 25000
#define AGG_CPY_BLK ((NNODES * 32) / 256)     // 6250
__global__ void agg_all() {
    if (blockIdx.x < AGG_SEG_BLK) {
        int seg  = blockIdx.x * 16 + (threadIdx.x >> 4);
        int lane = threadIdx.x & 15;
        int beg = d_off[seg], end = d_off[seg + 1];
        int dst = seg >> 3, r = seg & 7;
        const uint4* xh4 = reinterpret_cast<const uint4*>(d_xh);
        float4 a01 = make_float4(0.f, 0.f, 0.f, 0.f);
        float4 a23 = make_float4(0.f, 0.f, 0.f, 0.f);
        for (int e = beg; e < end; e++) {
            uint4 hq = __ldg(&xh4[(size_t)d_ssrc[e] * 16 + lane]);
            float2 f0 = __half22float2(*(const __half2*)&hq.x);
            float2 f1 = __half22float2(*(const __half2*)&hq.y);
            float2 f2 = __half22float2(*(const __half2*)&hq.z);
            float2 f3 = __half22float2(*(const __half2*)&hq.w);
            a01.x += f0.x; a01.y += f0.y; a01.z += f1.x; a01.w += f1.y;
            a23.x += f2.x; a23.y += f2.y; a23.z += f3.x; a23.w += f3.y;
        }
        float inv = (end > beg) ? 1.0f / (float)(end - beg) : 0.0f;
        __align__(16) __half hv[8];
        hv[0] = __float2half(a01.x * inv); hv[1] = __float2half(a01.y * inv);
        hv[2] = __float2half(a01.z * inv); hv[3] = __float2half(a01.w * inv);
        hv[4] = __float2half(a23.x * inv); hv[5] = __float2half(a23.y * inv);
        hv[6] = __float2half(a23.z * inv); hv[7] = __float2half(a23.w * inv);
        *(uint4*)&d_Ah[(size_t)dst * NK + r * 128 + lane * 8] = *(uint4*)hv;
    } else {
        int ci = (blockIdx.x - AGG_SEG_BLK) * 256 + threadIdx.x;
        int row = ci >> 5, l = ci & 31;
        uint2 v = *(const uint2*)&d_xh[(size_t)row * 128 + l * 4];
        *(uint2*)&d_Ah[(size_t)row * NK + 1024 + l * 4] = v;
    }
}

// ---------------- wmma GEMMs (plain fp16 operands) ----------------
typedef wmma::fragment<wmma::matrix_a, 16, 16, 16, __half, wmma::row_major> FragA;
typedef wmma::fragment<wmma::matrix_b, 16, 16, 16, __half, wmma::col_major> FragB;
typedef wmma::fragment<wmma::accumulator, 16, 16, 16, float> FragC;

#define STAGE_B 20480
#define NSTG    3
#define GSMEM   67584

__device__ __forceinline__ void mma_block(char* sm, int st, int wm, int wn, FragC acc[2][4]) {
    __half* p = (__half*)(sm + st * STAGE_B);
    #pragma unroll
    for (int kk = 0; kk < 32; kk += 16) {
        FragA fa[2];
        #pragma unroll
        for (int i = 0; i < 2; i++)
            wmma::load_matrix_sync(fa[i], p + (wm + i * 16) * 40 + kk, 40);
        #pragma unroll
        for (int j = 0; j < 4; j++) {
            FragB fb;
            wmma::load_matrix_sync(fb, p + 5120 + (wn + j * 16) * 40 + kk, 40);
            #pragma unroll
            for (int i = 0; i < 2; i++)
                wmma::mma_sync(acc[i][j], fa[i], fb, acc[i][j]);
        }
    }
}

__global__ void __launch_bounds__(256, 2) gemm1_wmma() {
    extern __shared__ __align__(16) char sm[];
    uint32_t sa = smem_u32(sm);
    int tid = threadIdx.x, wid = tid >> 5;
    int m0 = blockIdx.x << 7;
    int kz = blockIdx.y;
    int wm = (wid & 3) << 5;
    int wn = (wid >> 2) << 6;

    FragC acc[2][4];
    #pragma unroll
    for (int i = 0; i < 2; i++)
        #pragma unroll
        for (int j = 0; j < 4; j++) wmma::fill_fragment(acc[i][j], 0.0f);

    int kbase = kz * (KCH * 32);
    auto issue = [&](int ch, int st) {
        int k0 = kbase + (ch << 5);
        uint32_t so = sa + st * STAGE_B;
        #pragma unroll
        for (int t = tid; t < 512; t += 256) {
            int row = t >> 2, c8 = (t & 3) << 3;
            int gr = m0 + row;
            int pr = (gr < NNODES) ? 16 : 0;
            int grc = (gr < NNODES) ? gr : 0;
            size_t ga = (size_t)grc * NK + k0 + c8;
            uint32_t ds = so + row * 80 + c8 * 2;
            cpa(ds, d_Ah + ga, pr);
            size_t gb = (size_t)row * NK + k0 + c8;
            cpa(ds + 10240, d_Bh + gb, 16);
        }
    };

    issue(0, 0); CP_COMMIT();
    issue(1, 1); CP_COMMIT();
    for (int ch = 0; ch < KCH; ch++) {
        if (ch + 2 < KCH) issue(ch + 2, (ch + 2) % NSTG);
        CP_COMMIT();
        CP_WAIT2();
        __syncthreads();
        mma_block(sm, ch % NSTG, wm, wn, acc);
        __syncthreads();
    }
    CP_WAIT0();

    float* P = d_P + (size_t)kz * MPAD * 128;
    #pragma unroll
    for (int i = 0; i < 2; i++)
        #pragma unroll
        for (int j = 0; j < 4; j++)
            wmma::store_matrix_sync(&P[(size_t)(m0 + wm + i * 16) * 128 + wn + j * 16],
                                    acc[i][j], 128, wmma::mem_row_major);
}

__global__ void finish_h(const float* __restrict__ bias1) {
    int idx = blockIdx.x * blockDim.x + threadIdx.x;
    if (idx >= NNODES * 32) return;
    int row = idx >> 5, c4 = (idx & 31) << 2;
    size_t o = (size_t)row * 128 + c4;
    float4 a = *(const float4*)&d_P[o];
    float4 b = *(const float4*)&d_P[(size_t)MPAD * 128 + o];
    float4 c = *(const float4*)&d_P[2 * (size_t)MPAD * 128 + o];
    __align__(8) __half hv[4];
    hv[0] = __float2half(a.x + b.x + c.x + bias1[c4]);
    hv[1] = __float2half(a.y + b.y + c.y + bias1[c4 + 1]);
    hv[2] = __float2half(a.z + b.z + c.z + bias1[c4 + 2]);
    hv[3] = __float2half(a.w + b.w + c.w + bias1[c4 + 3]);
    *(uint2*)&d_hh[o] = *(uint2*)hv;
}

__global__ void __launch_bounds__(256, 2) gemm2_wmma() {
    extern __shared__ __align__(16) char sm[];
    uint32_t sa = smem_u32(sm);
    int tid = threadIdx.x, wid = tid >> 5;
    int m0 = blockIdx.x << 7;
    int n0 = blockIdx.y << 7;
    int wm = (wid & 3) << 5;
    int wn = (wid >> 2) << 6;

    FragC acc[2][4];
    #pragma unroll
    for (int i = 0; i < 2; i++)
        #pragma unroll
        for (int j = 0; j < 4; j++) wmma::fill_fragment(acc[i][j], 0.0f);

    auto issue = [&](int ch, int st) {
        int k0 = ch << 5;
        uint32_t so = sa + st * STAGE_B;
        #pragma unroll
        for (int t = tid; t < 512; t += 256) {
            int row = t >> 2, c8 = (t & 3) << 3;
            int gr = m0 + row;
            int pr = (gr < NNODES) ? 16 : 0;
            int grc = (gr < NNODES) ? gr : 0;
            size_t ga = (size_t)grc * 128 + k0 + c8;
            uint32_t ds = so + row * 80 + c8 * 2;
            cpa(ds, d_hh + ga, pr);
            size_t gb = (size_t)(n0 + row) * 128 + k0 + c8;
            cpa(ds + 10240, d_Ch + gb, 16);
        }
    };

    issue(0, 0); CP_COMMIT();
    issue(1, 1); CP_COMMIT();
    for (int ch = 0; ch < 4; ch++) {
        if (ch + 2 < 4) issue(ch + 2, (ch + 2) % NSTG);
        CP_COMMIT();
        CP_WAIT2();
        __syncthreads();
        mma_block(sm, ch % NSTG, wm, wn, acc);
        __syncthreads();
    }
    CP_WAIT0();
    __syncthreads();

    float* sC = (float*)sm;
    #pragma unroll
    for (int i = 0; i < 2; i++)
        #pragma unroll
        for (int j = 0; j < 4; j++)
            wmma::store_matrix_sync(&sC[(wm + i * 16) * 132 + wn + j * 16],
                                    acc[i][j], 132, wmma::mem_row_major);
    __syncthreads();
    int sel = n0 >> 7;
    for (int t = tid; t < 4096; t += 256) {
        int row = t >> 5, c4 = (t & 31) << 2;
        int gr = m0 + row;
        if (gr >= NNODES) continue;
        const float* p = &sC[row * 132 + c4];
        int c = n0 + c4;
        float v0 = p[0] + d_bcat[c],     v1 = p[1] + d_bcat[c + 1];
        float v2 = p[2] + d_bcat[c + 2], v3 = p[3] + d_bcat[c + 3];
        if (sel == 0 || sel == 3) {
            float* dst = &d_kskip[(size_t)gr * 256 + ((sel == 0) ? c4 : 128 + c4)];
            *(float4*)dst = make_float4(v0, v1, v2, v3);
        } else {
            __align__(8) __half hv[4];
            hv[0] = __float2half(v0); hv[1] = __float2half(v1);
            hv[2] = __float2half(v2); hv[3] = __float2half(v3);
            __half* dst = &d_qvh[(size_t)gr * 256 + ((sel == 1) ? c4 : 128 + c4)];
            *(uint2*)dst = *(uint2*)hv;
        }
    }
}

// ---------------- gate: 16 lanes per dst, 2 dst per warp ----------------
__global__ void gate_kernel(float* __restrict__ out) {
    int dst = blockIdx.x * 16 + (threadIdx.x >> 4);
    if (dst >= NNODES) return;
    int lane = threadIdx.x & 15;
    const float4* ks4 = reinterpret_cast<const float4*>(d_kskip);   // 64 float4/row
    const uint4*  qv4 = reinterpret_cast<const uint4*>(d_qvh);      // 32 uint4/row
    float4 kd0 = ks4[(size_t)dst * 64 + lane * 2];
    float4 kd1 = ks4[(size_t)dst * 64 + lane * 2 + 1];
    float4 ac0 = ks4[(size_t)dst * 64 + 32 + lane * 2];
    float4 ac1 = ks4[(size_t)dst * 64 + 32 + lane * 2 + 1];
    int beg = d_off[dst * NREL];
    int end = d_off[dst * NREL + NREL];
    for (int e = beg; e < end; e++) {
        int s = d_ssrc[e];
        uint4 qr = __ldg(&qv4[(size_t)s * 32 + lane]);
        uint4 vr = __ldg(&qv4[(size_t)s * 32 + 16 + lane]);
        float2 q0 = __half22float2(*(const __half2*)&qr.x);
        float2 q1 = __half22float2(*(const __half2*)&qr.y);
        float2 q2 = __half22float2(*(const __half2*)&qr.z);
        float2 q3 = __half22float2(*(const __half2*)&qr.w);
        float2 v0 = __half22float2(*(const __half2*)&vr.x);
        float2 v1 = __half22float2(*(const __half2*)&vr.y);
        float2 v2 = __half22float2(*(const __half2*)&vr.z);
        float2 v3 = __half22float2(*(const __half2*)&vr.w);
        ac0.x += v0.x * sigf(kd0.x + q0.x);
        ac0.y += v0.y * sigf(kd0.y + q0.y);
        ac0.z += v1.x * sigf(kd0.z + q1.x);
        ac0.w += v1.y * sigf(kd0.w + q1.y);
        ac1.x += v2.x * sigf(kd1.x + q2.x);
        ac1.y += v2.y * sigf(kd1.y + q2.y);
        ac1.z += v3.x * sigf(kd1.z + q3.x);
        ac1.w += v3.y * sigf(kd1.w + q3.y);
    }
    float4* out4 = reinterpret_cast<float4*>(out);
    out4[(size_t)dst * 32 + lane * 2]     = ac0;
    out4[(size_t)dst * 32 + lane * 2 + 1] = ac1;
}

// ---------------- launcher ----------------
extern "C" void kernel_launch(void* const* d_in, const int* in_sizes, int n_in,
                              void* d_out, int out_size) {
    const float* x     = (const float*)d_in[0];
    const int*   ei    = (const int*)  d_in[1];
    const int*   etype = (const int*)  d_in[3];
    const float* basis = (const float*)d_in[4];
    const float* comp  = (const float*)d_in[5];
    const float* root  = (const float*)d_in[6];
    const float* bias1 = (const float*)d_in[7];
    const float* wk = (const float*)d_in[8];  const float* bk = (const float*)d_in[9];
    const float* wq = (const float*)d_in[10]; const float* bq = (const float*)d_in[11];
    const float* wv = (const float*)d_in[12]; const float* bv = (const float*)d_in[13];
    const float* ws = (const float*)d_in[14]; const float* bs = (const float*)d_in[15];
    float* out = (float*)d_out;

    cudaFuncSetAttribute(gemm1_wmma, cudaFuncAttributeMaxDynamicSharedMemorySize, GSMEM);
    cudaFuncSetAttribute(gemm2_wmma, cudaFuncAttributeMaxDynamicSharedMemorySize, GSMEM);

    convert_xh<<<(NNODES * 32 + 255) / 256, 256>>>(x);
    prep_weights<<<(128 * NK + 512 * 128 + 255) / 256, 256>>>(comp, basis, root,
                                                              wk, bk, wq, bq, wv, bv, ws, bs);

    count_edges<<<(NEDGES + 255) / 256, 256>>>(ei, etype);
    scan_blocksum<<<NSCAN, SCAN_B>>>();
    scan_partials<<<1, SCAN_B>>>();
    scan_final<<<NSCAN, SCAN_B>>>();
    scatter_edges<<<(NEDGES + 255) / 256, 256>>>(ei, etype);

    agg_all<<<AGG_SEG_BLK + AGG_CPY_BLK, 256>>>();

    gemm1_wmma<<<dim3(MT, KZ), 256, GSMEM>>>();
    finish_h<<<(NNODES * 32 + 511) / 512, 512>>>(bias1);
    gemm2_wmma<<<dim3(MT, 4), 256, GSMEM>>>();

    gate_kernel<<<(NNODES + 15) / 16, 256>>>(out);
}

// round 15
// speedup vs baseline: 1.0704x; 1.0704x over previous
#include <cuda_runtime.h>
#include <cuda_fp16.h>
#include <mma.h>
#include <cstdint>

using namespace nvcuda;

#define NNODES 50000
#define NEDGES 600000
#define NREL   8
#define NBASIS 32
#define RN     (NREL * NNODES)
#define SCAN_B 1024
#define NSCAN  ((RN + SCAN_B - 1) / SCAN_B)
#define NK     1152
#define MT     ((NNODES + 127) / 128)    // 391
#define MPAD   (MT * 128)                // 50048
#define KZ     3
#define KCH    12                         // 3 * 12 * 32 = 1152

// ---------------- static device scratch ----------------
static __device__ __align__(16) __half d_xh[(size_t)NNODES * 128];
static __device__ __align__(16) __half d_Ah[(size_t)NNODES * NK];
static __device__ __align__(16) __half d_Bh[128 * NK];
static __device__ __align__(16) __half d_Ch[512 * 128];
static __device__ __align__(16) float d_bcat[512];
static __device__ __align__(16) __half d_hh[(size_t)NNODES * 128];
static __device__ __align__(16) float d_P[KZ * (size_t)MPAD * 128];
static __device__ __align__(16) float d_kskip[(size_t)NNODES * 256];
static __device__ __align__(16) __half d_qvh[(size_t)NNODES * 256];
static __device__ int d_cnt[RN];
static __device__ int d_off[RN + 1];
static __device__ int d_cur[RN];
static __device__ int d_ssrc[NEDGES];
static __device__ int d_part[SCAN_B];
static __device__ int d_ppre[SCAN_B];

// ---------------- helpers ----------------
__device__ __forceinline__ float sigf(float z) { return 1.0f / (1.0f + __expf(-z)); }
__device__ __forceinline__ uint32_t smem_u32(const void* p) {
    uint32_t a;
    asm("{ .reg .u64 t; cvta.to.shared.u64 t, %1; cvt.u32.u64 %0, t; }" : "=r"(a) : "l"(p));
    return a;
}
__device__ __forceinline__ void cpa(uint32_t d, const void* s, int srcsz) {
    asm volatile("cp.async.cg.shared.global [%0], [%1], 16, %2;"
                 :: "r"(d), "l"(s), "r"(srcsz) : "memory");
}
#define CP_COMMIT() asm volatile("cp.async.commit_group;" ::: "memory")
#define CP_WAIT2()  asm volatile("cp.async.wait_group 2;" ::: "memory")
#define CP_WAIT0()  asm volatile("cp.async.wait_group 0;" ::: "memory")

// ---------------- x -> fp16, zero d_cnt ----------------
__global__ void convert_xh(const float* __restrict__ x) {
    int idx = blockIdx.x * blockDim.x + threadIdx.x;
    if (idx < RN) d_cnt[idx] = 0;
    if (idx >= NNODES * 32) return;
    float4 v = reinterpret_cast<const float4*>(x)[idx];
    __align__(8) __half hv[4];
    hv[0] = __float2half(v.x); hv[1] = __float2half(v.y);
    hv[2] = __float2half(v.z); hv[3] = __float2half(v.w);
    *(uint2*)&d_xh[(size_t)idx * 4] = *(uint2*)hv;
}

// ---------------- fused weight prep ----------------
__global__ void prep_weights(const float* __restrict__ comp, const float* __restrict__ basis,
                             const float* __restrict__ root,
                             const float* wk, const float* bk, const float* wq, const float* bq,
                             const float* wv, const float* bv, const float* ws, const float* bs) {
    int idx = blockIdx.x * blockDim.x + threadIdx.x;
    if (idx < 128 * NK) {
        int n = idx / NK, k = idx % NK;
        float w;
        if (k < 1024) {
            int r = k >> 7, i = k & 127;
            float s = 0.0f;
            #pragma unroll
            for (int b = 0; b < NBASIS; b++)
                s += comp[r * NBASIS + b] * basis[(b * 128 + i) * 128 + n];
            w = s;
        } else {
            w = root[(k - 1024) * 128 + n];
        }
        d_Bh[idx] = __float2half(w);
        return;
    }
    int j = idx - 128 * NK;
    if (j >= 512 * 128) return;
    int n = j >> 7, k = j & 127;
    int sel = n >> 7, cc = n & 127;
    const float* W = (sel == 0) ? wk : (sel == 1) ? wq : (sel == 2) ? wv : ws;
    d_Ch[j] = __float2half(W[k * 128 + cc]);
    if (k == 0) {
        const float* B = (sel == 0) ? bk : (sel == 1) ? bq : (sel == 2) ? bv : bs;
        d_bcat[n] = B[cc];
    }
}

// ---------------- CSR build ----------------
__global__ void count_edges(const int* __restrict__ ei, const int* __restrict__ etype) {
    int e = blockIdx.x * blockDim.x + threadIdx.x;
    if (e >= NEDGES) return;
    atomicAdd(&d_cnt[ei[NEDGES + e] * NREL + etype[e]], 1);
}

// warp-shuffle block sum
__global__ void scan_blocksum() {
    int tid = threadIdx.x, gid = blockIdx.x * SCAN_B + tid;
    int lane = tid & 31, wid = tid >> 5;
    int v = (gid < RN) ? d_cnt[gid] : 0;
    #pragma unroll
    for (int o = 16; o > 0; o >>= 1) v += __shfl_down_sync(0xFFFFFFFFu, v, o);
    __shared__ int ws[32];
    if (lane == 0) ws[wid] = v;
    __syncthreads();
    if (wid == 0) {
        int t = ws[lane];
        #pragma unroll
        for (int o = 16; o > 0; o >>= 1) t += __shfl_down_sync(0xFFFFFFFFu, t, o);
        if (lane == 0) d_part[blockIdx.x] = t;
    }
}

// warp-shuffle inclusive scan -> exclusive prefix of block sums
__global__ void scan_partials() {
    int tid = threadIdx.x, lane = tid & 31, wid = tid >> 5;
    int v = (tid < NSCAN) ? d_part[tid] : 0;
    int x = v;
    #pragma unroll
    for (int o = 1; o < 32; o <<= 1) {
        int t = __shfl_up_sync(0xFFFFFFFFu, x, o);
        if (lane >= o) x += t;
    }
    __shared__ int ws[32];
    if (lane == 31) ws[wid] = x;
    __syncthreads();
    if (wid == 0) {
        int t = ws[lane];
        #pragma unroll
        for (int o = 1; o < 32; o <<= 1) {
            int u = __shfl_up_sync(0xFFFFFFFFu, t, o);
            if (lane >= o) t += u;
        }
        ws[lane] = t;
    }
    __syncthreads();
    int base = (wid > 0) ? ws[wid - 1] : 0;
    d_ppre[tid] = base + x - v;
}

// warp-shuffle block scan + global offset
__global__ void scan_final() {
    int tid = threadIdx.x, gid = blockIdx.x * SCAN_B + tid;
    int lane = tid & 31, wid = tid >> 5;
    int v = (gid < RN) ? d_cnt[gid] : 0;
    int x = v;
    #pragma unroll
    for (int o = 1; o < 32; o <<= 1) {
        int t = __shfl_up_sync(0xFFFFFFFFu, x, o);
        if (lane >= o) x += t;
    }
    __shared__ int ws[32];
    if (lane == 31) ws[wid] = x;
    __syncthreads();
    if (wid == 0) {
        int t = ws[lane];
        #pragma unroll
        for (int o = 1; o < 32; o <<= 1) {
            int u = __shfl_up_sync(0xFFFFFFFFu, t, o);
            if (lane >= o) t += u;
        }
        ws[lane] = t;
    }
    __syncthreads();
    int base = (wid > 0) ? ws[wid - 1] : 0;
    int ex = base + x - v + d_ppre[blockIdx.x];
    if (gid < RN) {
        d_off[gid] = ex; d_cur[gid] = ex;
        if (gid == RN - 1) d_off[RN] = ex + v;
    }
}

__global__ void scatter_edges(const int* __restrict__ ei, const int* __restrict__ etype) {
    int e = blockIdx.x * blockDim.x + threadIdx.x;
    if (e >= NEDGES) return;
    int pos = atomicAdd(&d_cur[ei[NEDGES + e] * NREL + etype[e]], 1);
    d_ssrc[pos] = ei[e];
}

// ---------------- gather + root copy, single launch ----------------
#define AGG_SEG_BLK (RN / 16)                 // 25000
#define AGG_CPY_BLK ((NNODES * 32) / 256)     // 6250
__global__ void agg_all() {
    if (blockIdx.x < AGG_SEG_BLK) {
        int seg  = blockIdx.x * 16 + (threadIdx.x >> 4);
        int lane = threadIdx.x & 15;
        int beg = d_off[seg], end = d_off[seg + 1];
        int dst = seg >> 3, r = seg & 7;
        const uint4* xh4 = reinterpret_cast<const uint4*>(d_xh);
        float4 a01 = make_float4(0.f, 0.f, 0.f, 0.f);
        float4 a23 = make_float4(0.f, 0.f, 0.f, 0.f);
        for (int e = beg; e < end; e++) {
            uint4 hq = __ldg(&xh4[(size_t)d_ssrc[e] * 16 + lane]);
            float2 f0 = __half22float2(*(const __half2*)&hq.x);
            float2 f1 = __half22float2(*(const __half2*)&hq.y);
            float2 f2 = __half22float2(*(const __half2*)&hq.z);
            float2 f3 = __half22float2(*(const __half2*)&hq.w);
            a01.x += f0.x; a01.y += f0.y; a01.z += f1.x; a01.w += f1.y;
            a23.x += f2.x; a23.y += f2.y; a23.z += f3.x; a23.w += f3.y;
        }
        float inv = (end > beg) ? 1.0f / (float)(end - beg) : 0.0f;
        __align__(16) __half hv[8];
        hv[0] = __float2half(a01.x * inv); hv[1] = __float2half(a01.y * inv);
        hv[2] = __float2half(a01.z * inv); hv[3] = __float2half(a01.w * inv);
        hv[4] = __float2half(a23.x * inv); hv[5] = __float2half(a23.y * inv);
        hv[6] = __float2half(a23.z * inv); hv[7] = __float2half(a23.w * inv);
        *(uint4*)&d_Ah[(size_t)dst * NK + r * 128 + lane * 8] = *(uint4*)hv;
    } else {
        int ci = (blockIdx.x - AGG_SEG_BLK) * 256 + threadIdx.x;
        int row = ci >> 5, l = ci & 31;
        uint2 v = *(const uint2*)&d_xh[(size_t)row * 128 + l * 4];
        *(uint2*)&d_Ah[(size_t)row * NK + 1024 + l * 4] = v;
    }
}

// ---------------- wmma GEMMs (plain fp16 operands) ----------------
typedef wmma::fragment<wmma::matrix_a, 16, 16, 16, __half, wmma::row_major> FragA;
typedef wmma::fragment<wmma::matrix_b, 16, 16, 16, __half, wmma::col_major> FragB;
typedef wmma::fragment<wmma::accumulator, 16, 16, 16, float> FragC;

#define STAGE_B 20480
#define NSTG    3
#define GSMEM   67584

__device__ __forceinline__ void mma_block(char* sm, int st, int wm, int wn, FragC acc[2][4]) {
    __half* p = (__half*)(sm + st * STAGE_B);
    #pragma unroll
    for (int kk = 0; kk < 32; kk += 16) {
        FragA fa[2];
        #pragma unroll
        for (int i = 0; i < 2; i++)
            wmma::load_matrix_sync(fa[i], p + (wm + i * 16) * 40 + kk, 40);
        #pragma unroll
        for (int j = 0; j < 4; j++) {
            FragB fb;
            wmma::load_matrix_sync(fb, p + 5120 + (wn + j * 16) * 40 + kk, 40);
            #pragma unroll
            for (int i = 0; i < 2; i++)
                wmma::mma_sync(acc[i][j], fa[i], fb, acc[i][j]);
        }
    }
}

__global__ void __launch_bounds__(256, 2) gemm1_wmma() {
    extern __shared__ __align__(16) char sm[];
    uint32_t sa = smem_u32(sm);
    int tid = threadIdx.x, wid = tid >> 5;
    int m0 = blockIdx.x << 7;
    int kz = blockIdx.y;
    int wm = (wid & 3) << 5;
    int wn = (wid >> 2) << 6;

    FragC acc[2][4];
    #pragma unroll
    for (int i = 0; i < 2; i++)
        #pragma unroll
        for (int j = 0; j < 4; j++) wmma::fill_fragment(acc[i][j], 0.0f);

    int kbase = kz * (KCH * 32);
    auto issue = [&](int ch, int st) {
        int k0 = kbase + (ch << 5);
        uint32_t so = sa + st * STAGE_B;
        #pragma unroll
        for (int t = tid; t < 512; t += 256) {
            int row = t >> 2, c8 = (t & 3) << 3;
            int gr = m0 + row;
            int pr = (gr < NNODES) ? 16 : 0;
            int grc = (gr < NNODES) ? gr : 0;
            size_t ga = (size_t)grc * NK + k0 + c8;
            uint32_t ds = so + row * 80 + c8 * 2;
            cpa(ds, d_Ah + ga, pr);
            size_t gb = (size_t)row * NK + k0 + c8;
            cpa(ds + 10240, d_Bh + gb, 16);
        }
    };

    issue(0, 0); CP_COMMIT();
    issue(1, 1); CP_COMMIT();
    for (int ch = 0; ch < KCH; ch++) {
        if (ch + 2 < KCH) issue(ch + 2, (ch + 2) % NSTG);
        CP_COMMIT();
        CP_WAIT2();
        __syncthreads();
        mma_block(sm, ch % NSTG, wm, wn, acc);
        __syncthreads();
    }
    CP_WAIT0();

    float* P = d_P + (size_t)kz * MPAD * 128;
    #pragma unroll
    for (int i = 0; i < 2; i++)
        #pragma unroll
        for (int j = 0; j < 4; j++)
            wmma::store_matrix_sync(&P[(size_t)(m0 + wm + i * 16) * 128 + wn + j * 16],
                                    acc[i][j], 128, wmma::mem_row_major);
}

__global__ void finish_h(const float* __restrict__ bias1) {
    int idx = blockIdx.x * blockDim.x + threadIdx.x;
    if (idx >= NNODES * 32) return;
    int row = idx >> 5, c4 = (idx & 31) << 2;
    size_t o = (size_t)row * 128 + c4;
    float4 a = *(const float4*)&d_P[o];
    float4 b = *(const float4*)&d_P[(size_t)MPAD * 128 + o];
    float4 c = *(const float4*)&d_P[2 * (size_t)MPAD * 128 + o];
    __align__(8) __half hv[4];
    hv[0] = __float2half(a.x + b.x + c.x + bias1[c4]);
    hv[1] = __float2half(a.y + b.y + c.y + bias1[c4 + 1]);
    hv[2] = __float2half(a.z + b.z + c.z + bias1[c4 + 2]);
    hv[3] = __float2half(a.w + b.w + c.w + bias1[c4 + 3]);
    *(uint2*)&d_hh[o] = *(uint2*)hv;
}

__global__ void __launch_bounds__(256, 2) gemm2_wmma() {
    extern __shared__ __align__(16) char sm[];
    uint32_t sa = smem_u32(sm);
    int tid = threadIdx.x, wid = tid >> 5;
    int m0 = blockIdx.x << 7;
    int n0 = blockIdx.y << 7;
    int wm = (wid & 3) << 5;
    int wn = (wid >> 2) << 6;

    FragC acc[2][4];
    #pragma unroll
    for (int i = 0; i < 2; i++)
        #pragma unroll
        for (int j = 0; j < 4; j++) wmma::fill_fragment(acc[i][j], 0.0f);

    auto issue = [&](int ch, int st) {
        int k0 = ch << 5;
        uint32_t so = sa + st * STAGE_B;
        #pragma unroll
        for (int t = tid; t < 512; t += 256) {
            int row = t >> 2, c8 = (t & 3) << 3;
            int gr = m0 + row;
            int pr = (gr < NNODES) ? 16 : 0;
            int grc = (gr < NNODES) ? gr : 0;
            size_t ga = (size_t)grc * 128 + k0 + c8;
            uint32_t ds = so + row * 80 + c8 * 2;
            cpa(ds, d_hh + ga, pr);
            size_t gb = (size_t)(n0 + row) * 128 + k0 + c8;
            cpa(ds + 10240, d_Ch + gb, 16);
        }
    };

    issue(0, 0); CP_COMMIT();
    issue(1, 1); CP_COMMIT();
    for (int ch = 0; ch < 4; ch++) {
        if (ch + 2 < 4) issue(ch + 2, (ch + 2) % NSTG);
        CP_COMMIT();
        CP_WAIT2();
        __syncthreads();
        mma_block(sm, ch % NSTG, wm, wn, acc);
        __syncthreads();
    }
    CP_WAIT0();
    __syncthreads();

    float* sC = (float*)sm;
    #pragma unroll
    for (int i = 0; i < 2; i++)
        #pragma unroll
        for (int j = 0; j < 4; j++)
            wmma::store_matrix_sync(&sC[(wm + i * 16) * 132 + wn + j * 16],
                                    acc[i][j], 132, wmma::mem_row_major);
    __syncthreads();
    int sel = n0 >> 7;
    for (int t = tid; t < 4096; t += 256) {
        int row = t >> 5, c4 = (t & 31) << 2;
        int gr = m0 + row;
        if (gr >= NNODES) continue;
        const float* p = &sC[row * 132 + c4];
        int c = n0 + c4;
        float v0 = p[0] + d_bcat[c],     v1 = p[1] + d_bcat[c + 1];
        float v2 = p[2] + d_bcat[c + 2], v3 = p[3] + d_bcat[c + 3];
        if (sel == 0 || sel == 3) {
            float* dst = &d_kskip[(size_t)gr * 256 + ((sel == 0) ? c4 : 128 + c4)];
            *(float4*)dst = make_float4(v0, v1, v2, v3);
        } else {
            __align__(8) __half hv[4];
            hv[0] = __float2half(v0); hv[1] = __float2half(v1);
            hv[2] = __float2half(v2); hv[3] = __float2half(v3);
            __half* dst = &d_qvh[(size_t)gr * 256 + ((sel == 1) ? c4 : 128 + c4)];
            *(uint2*)dst = *(uint2*)hv;
        }
    }
}

// ---------------- gate: fp32 k/skip, fp16 q/v (32-lane, R13 form) ----------------
__global__ void gate_kernel(float* __restrict__ out) {
    int dst = blockIdx.x * 8 + (threadIdx.x >> 5);
    if (dst >= NNODES) return;
    int lane = threadIdx.x & 31;
    const float4* ks4 = reinterpret_cast<const float4*>(d_kskip);
    const uint2*  qv2 = reinterpret_cast<const uint2*>(d_qvh);
    float4 kd  = ks4[(size_t)dst * 64 + lane];
    float4 acc = ks4[(size_t)dst * 64 + 32 + lane];
    int beg = d_off[dst * NREL];
    int end = d_off[dst * NREL + NREL];
    for (int e = beg; e < end; e++) {
        int s = d_ssrc[e];
        uint2 qr = __ldg(&qv2[(size_t)s * 64 + lane]);
        uint2 vr = __ldg(&qv2[(size_t)s * 64 + 32 + lane]);
        float2 q01 = __half22float2(*(const __half2*)&qr.x);
        float2 q23 = __half22float2(*(const __half2*)&qr.y);
        float2 v01 = __half22float2(*(const __half2*)&vr.x);
        float2 v23 = __half22float2(*(const __half2*)&vr.y);
        acc.x += v01.x * sigf(kd.x + q01.x);
        acc.y += v01.y * sigf(kd.y + q01.y);
        acc.z += v23.x * sigf(kd.z + q23.x);
        acc.w += v23.y * sigf(kd.w + q23.y);
    }
    reinterpret_cast<float4*>(out)[(size_t)dst * 32 + lane] = acc;
}

// ---------------- launcher ----------------
extern "C" void kernel_launch(void* const* d_in, const int* in_sizes, int n_in,
                              void* d_out, int out_size) {
    const float* x     = (const float*)d_in[0];
    const int*   ei    = (const int*)  d_in[1];
    const int*   etype = (const int*)  d_in[3];
    const float* basis = (const float*)d_in[4];
    const float* comp  = (const float*)d_in[5];
    const float* root  = (const float*)d_in[6];
    const float* bias1 = (const float*)d_in[7];
    const float* wk = (const float*)d_in[8];  const float* bk = (const float*)d_in[9];
    const float* wq = (const float*)d_in[10]; const float* bq = (const float*)d_in[11];
    const float* wv = (const float*)d_in[12]; const float* bv = (const float*)d_in[13];
    const float* ws = (const float*)d_in[14]; const float* bs = (const float*)d_in[15];
    float* out = (float*)d_out;

    cudaFuncSetAttribute(gemm1_wmma, cudaFuncAttributeMaxDynamicSharedMemorySize, GSMEM);
    cudaFuncSetAttribute(gemm2_wmma, cudaFuncAttributeMaxDynamicSharedMemorySize, GSMEM);

    convert_xh<<<(NNODES * 32 + 255) / 256, 256>>>(x);
    prep_weights<<<(128 * NK + 512 * 128 + 255) / 256, 256>>>(comp, basis, root,
                                                              wk, bk, wq, bq, wv, bv, ws, bs);

    count_edges<<<(NEDGES + 255) / 256, 256>>>(ei, etype);
    scan_blocksum<<<NSCAN, SCAN_B>>>();
    scan_partials<<<1, SCAN_B>>>();
    scan_final<<<NSCAN, SCAN_B>>>();
    scatter_edges<<<(NEDGES + 255) / 256, 256>>>(ei, etype);

    agg_all<<<AGG_SEG_BLK + AGG_CPY_BLK, 256>>>();

    gemm1_wmma<<<dim3(MT, KZ), 256, GSMEM>>>();
    finish_h<<<(NNODES * 32 + 511) / 512, 512>>>(bias1);
    gemm2_wmma<<<dim3(MT, 4), 256, GSMEM>>>();

    gate_kernel<<<(NNODES + 7) / 8, 256>>>(out);
}

// round 16
// speedup vs baseline: 1.2648x; 1.1816x over previous
#include <cuda_runtime.h>
#include <cuda_fp16.h>
#include <mma.h>
#include <cstdint>

using namespace nvcuda;

#define NNODES 50000
#define NEDGES 600000
#define NREL   8
#define NBASIS 32
#define RN     (NREL * NNODES)
#define SCAN_B 1024
#define NSCAN  ((RN + SCAN_B - 1) / SCAN_B)
#define NK     1152
#define MT     ((NNODES + 127) / 128)    // 391
#define MPAD   (MT * 128)                // 50048
#define KZ     3
#define KCH    12                         // 3 * 12 * 32 = 1152

// ---------------- static device scratch ----------------
static __device__ __align__(16) __half d_xh[(size_t)NNODES * 128];
static __device__ __align__(16) __half d_Ah[(size_t)NNODES * NK];
static __device__ __align__(16) __half d_Bh[128 * NK];
static __device__ __align__(16) __half d_Ch[512 * 128];
static __device__ __align__(16) float d_bcat[512];
static __device__ __align__(16) __half d_hh[(size_t)NNODES * 128];
static __device__ __align__(16) float d_P[KZ * (size_t)MPAD * 128];
static __device__ __align__(16) float d_kskip[(size_t)NNODES * 256];
static __device__ __align__(16) __half d_qvh[(size_t)NNODES * 256];
static __device__ int d_cnt[RN];
static __device__ int d_off[RN + 1];
static __device__ int d_cur[RN];
static __device__ int d_ssrc[NEDGES];
static __device__ int d_part[SCAN_B];
static __device__ int d_ppre[SCAN_B];

// ---------------- helpers ----------------
// sigmoid via hardware tanh.approx: 1 MUFU op instead of 2 (EX2+RCP)
__device__ __forceinline__ float sigf(float z) {
    float t;
    asm("tanh.approx.f32 %0, %1;" : "=f"(t) : "f"(z * 0.5f));
    return fmaf(0.5f, t, 0.5f);
}
__device__ __forceinline__ uint32_t smem_u32(const void* p) {
    uint32_t a;
    asm("{ .reg .u64 t; cvta.to.shared.u64 t, %1; cvt.u32.u64 %0, t; }" : "=r"(a) : "l"(p));
    return a;
}
__device__ __forceinline__ void cpa(uint32_t d, const void* s, int srcsz) {
    asm volatile("cp.async.cg.shared.global [%0], [%1], 16, %2;"
                 :: "r"(d), "l"(s), "r"(srcsz) : "memory");
}
#define CP_COMMIT() asm volatile("cp.async.commit_group;" ::: "memory")
#define CP_WAIT2()  asm volatile("cp.async.wait_group 2;" ::: "memory")
#define CP_WAIT0()  asm volatile("cp.async.wait_group 0;" ::: "memory")

// ---------------- x -> fp16, zero d_cnt ----------------
__global__ void convert_xh(const float* __restrict__ x) {
    int idx = blockIdx.x * blockDim.x + threadIdx.x;
    if (idx < RN) d_cnt[idx] = 0;
    if (idx >= NNODES * 32) return;
    float4 v = reinterpret_cast<const float4*>(x)[idx];
    __align__(8) __half hv[4];
    hv[0] = __float2half(v.x); hv[1] = __float2half(v.y);
    hv[2] = __float2half(v.z); hv[3] = __float2half(v.w);
    *(uint2*)&d_xh[(size_t)idx * 4] = *(uint2*)hv;
}

// ---------------- fused weight prep ----------------
__global__ void prep_weights(const float* __restrict__ comp, const float* __restrict__ basis,
                             const float* __restrict__ root,
                             const float* wk, const float* bk, const float* wq, const float* bq,
                             const float* wv, const float* bv, const float* ws, const float* bs) {
    int idx = blockIdx.x * blockDim.x + threadIdx.x;
    if (idx < 128 * NK) {
        int n = idx / NK, k = idx % NK;
        float w;
        if (k < 1024) {
            int r = k >> 7, i = k & 127;
            float s = 0.0f;
            #pragma unroll
            for (int b = 0; b < NBASIS; b++)
                s += comp[r * NBASIS + b] * basis[(b * 128 + i) * 128 + n];
            w = s;
        } else {
            w = root[(k - 1024) * 128 + n];
        }
        d_Bh[idx] = __float2half(w);
        return;
    }
    int j = idx - 128 * NK;
    if (j >= 512 * 128) return;
    int n = j >> 7, k = j & 127;
    int sel = n >> 7, cc = n & 127;
    const float* W = (sel == 0) ? wk : (sel == 1) ? wq : (sel == 2) ? wv : ws;
    d_Ch[j] = __float2half(W[k * 128 + cc]);
    if (k == 0) {
        const float* B = (sel == 0) ? bk : (sel == 1) ? bq : (sel == 2) ? bv : bs;
        d_bcat[n] = B[cc];
    }
}

// ---------------- CSR build ----------------
__global__ void count_edges(const int* __restrict__ ei, const int* __restrict__ etype) {
    int e = blockIdx.x * blockDim.x + threadIdx.x;
    if (e >= NEDGES) return;
    atomicAdd(&d_cnt[ei[NEDGES + e] * NREL + etype[e]], 1);
}

// warp-shuffle block sum
__global__ void scan_blocksum() {
    int tid = threadIdx.x, gid = blockIdx.x * SCAN_B + tid;
    int lane = tid & 31, wid = tid >> 5;
    int v = (gid < RN) ? d_cnt[gid] : 0;
    #pragma unroll
    for (int o = 16; o > 0; o >>= 1) v += __shfl_down_sync(0xFFFFFFFFu, v, o);
    __shared__ int ws[32];
    if (lane == 0) ws[wid] = v;
    __syncthreads();
    if (wid == 0) {
        int t = ws[lane];
        #pragma unroll
        for (int o = 16; o > 0; o >>= 1) t += __shfl_down_sync(0xFFFFFFFFu, t, o);
        if (lane == 0) d_part[blockIdx.x] = t;
    }
}

// warp-shuffle inclusive scan -> exclusive prefix of block sums
__global__ void scan_partials() {
    int tid = threadIdx.x, lane = tid & 31, wid = tid >> 5;
    int v = (tid < NSCAN) ? d_part[tid] : 0;
    int x = v;
    #pragma unroll
    for (int o = 1; o < 32; o <<= 1) {
        int t = __shfl_up_sync(0xFFFFFFFFu, x, o);
        if (lane >= o) x += t;
    }
    __shared__ int ws[32];
    if (lane == 31) ws[wid] = x;
    __syncthreads();
    if (wid == 0) {
        int t = ws[lane];
        #pragma unroll
        for (int o = 1; o < 32; o <<= 1) {
            int u = __shfl_up_sync(0xFFFFFFFFu, t, o);
            if (lane >= o) t += u;
        }
        ws[lane] = t;
    }
    __syncthreads();
    int base = (wid > 0) ? ws[wid - 1] : 0;
    d_ppre[tid] = base + x - v;
}

// warp-shuffle block scan + global offset
__global__ void scan_final() {
    int tid = threadIdx.x, gid = blockIdx.x * SCAN_B + tid;
    int lane = tid & 31, wid = tid >> 5;
    int v = (gid < RN) ? d_cnt[gid] : 0;
    int x = v;
    #pragma unroll
    for (int o = 1; o < 32; o <<= 1) {
        int t = __shfl_up_sync(0xFFFFFFFFu, x, o);
        if (lane >= o) x += t;
    }
    __shared__ int ws[32];
    if (lane == 31) ws[wid] = x;
    __syncthreads();
    if (wid == 0) {
        int t = ws[lane];
        #pragma unroll
        for (int o = 1; o < 32; o <<= 1) {
            int u = __shfl_up_sync(0xFFFFFFFFu, t, o);
            if (lane >= o) t += u;
        }
        ws[lane] = t;
    }
    __syncthreads();
    int base = (wid > 0) ? ws[wid - 1] : 0;
    int ex = base + x - v + d_ppre[blockIdx.x];
    if (gid < RN) {
        d_off[gid] = ex; d_cur[gid] = ex;
        if (gid == RN - 1) d_off[RN] = ex + v;
    }
}

__global__ void scatter_edges(const int* __restrict__ ei, const int* __restrict__ etype) {
    int e = blockIdx.x * blockDim.x + threadIdx.x;
    if (e >= NEDGES) return;
    int pos = atomicAdd(&d_cur[ei[NEDGES + e] * NREL + etype[e]], 1);
    d_ssrc[pos] = ei[e];
}

// ---------------- gather + root copy, single launch ----------------
#define AGG_SEG_BLK (RN / 16)                 // 25000
#define AGG_CPY_BLK ((NNODES * 32) / 256)     // 6250
__global__ void agg_all() {
    if (blockIdx.x < AGG_SEG_BLK) {
        int seg  = blockIdx.x * 16 + (threadIdx.x >> 4);
        int lane = threadIdx.x & 15;
        int beg = d_off[seg], end = d_off[seg + 1];
        int dst = seg >> 3, r = seg & 7;
        const uint4* xh4 = reinterpret_cast<const uint4*>(d_xh);
        float4 a01 = make_float4(0.f, 0.f, 0.f, 0.f);
        float4 a23 = make_float4(0.f, 0.f, 0.f, 0.f);
        for (int e = beg; e < end; e++) {
            uint4 hq = __ldg(&xh4[(size_t)d_ssrc[e] * 16 + lane]);
            float2 f0 = __half22float2(*(const __half2*)&hq.x);
            float2 f1 = __half22float2(*(const __half2*)&hq.y);
            float2 f2 = __half22float2(*(const __half2*)&hq.z);
            float2 f3 = __half22float2(*(const __half2*)&hq.w);
            a01.x += f0.x; a01.y += f0.y; a01.z += f1.x; a01.w += f1.y;
            a23.x += f2.x; a23.y += f2.y; a23.z += f3.x; a23.w += f3.y;
        }
        float inv = (end > beg) ? 1.0f / (float)(end - beg) : 0.0f;
        __align__(16) __half hv[8];
        hv[0] = __float2half(a01.x * inv); hv[1] = __float2half(a01.y * inv);
        hv[2] = __float2half(a01.z * inv); hv[3] = __float2half(a01.w * inv);
        hv[4] = __float2half(a23.x * inv); hv[5] = __float2half(a23.y * inv);
        hv[6] = __float2half(a23.z * inv); hv[7] = __float2half(a23.w * inv);
        *(uint4*)&d_Ah[(size_t)dst * NK + r * 128 + lane * 8] = *(uint4*)hv;
    } else {
        int ci = (blockIdx.x - AGG_SEG_BLK) * 256 + threadIdx.x;
        int row = ci >> 5, l = ci & 31;
        uint2 v = *(const uint2*)&d_xh[(size_t)row * 128 + l * 4];
        *(uint2*)&d_Ah[(size_t)row * NK + 1024 + l * 4] = v;
    }
}

// ---------------- wmma GEMMs (plain fp16 operands) ----------------
typedef wmma::fragment<wmma::matrix_a, 16, 16, 16, __half, wmma::row_major> FragA;
typedef wmma::fragment<wmma::matrix_b, 16, 16, 16, __half, wmma::col_major> FragB;
typedef wmma::fragment<wmma::accumulator, 16, 16, 16, float> FragC;

#define STAGE_B 20480
#define NSTG    3
#define GSMEM   67584

__device__ __forceinline__ void mma_block(char* sm, int st, int wm, int wn, FragC acc[2][4]) {
    __half* p = (__half*)(sm + st * STAGE_B);
    #pragma unroll
    for (int kk = 0; kk < 32; kk += 16) {
        FragA fa[2];
        #pragma unroll
        for (int i = 0; i < 2; i++)
            wmma::load_matrix_sync(fa[i], p + (wm + i * 16) * 40 + kk, 40);
        #pragma unroll
        for (int j = 0; j < 4; j++) {
            FragB fb;
            wmma::load_matrix_sync(fb, p + 5120 + (wn + j * 16) * 40 + kk, 40);
            #pragma unroll
            for (int i = 0; i < 2; i++)
                wmma::mma_sync(acc[i][j], fa[i], fb, acc[i][j]);
        }
    }
}

__global__ void __launch_bounds__(256, 2) gemm1_wmma() {
    extern __shared__ __align__(16) char sm[];
    uint32_t sa = smem_u32(sm);
    int tid = threadIdx.x, wid = tid >> 5;
    int m0 = blockIdx.x << 7;
    int kz = blockIdx.y;
    int wm = (wid & 3) << 5;
    int wn = (wid >> 2) << 6;

    FragC acc[2][4];
    #pragma unroll
    for (int i = 0; i < 2; i++)
        #pragma unroll
        for (int j = 0; j < 4; j++) wmma::fill_fragment(acc[i][j], 0.0f);

    int kbase = kz * (KCH * 32);
    auto issue = [&](int ch, int st) {
        int k0 = kbase + (ch << 5);
        uint32_t so = sa + st * STAGE_B;
        #pragma unroll
        for (int t = tid; t < 512; t += 256) {
            int row = t >> 2, c8 = (t & 3) << 3;
            int gr = m0 + row;
            int pr = (gr < NNODES) ? 16 : 0;
            int grc = (gr < NNODES) ? gr : 0;
            size_t ga = (size_t)grc * NK + k0 + c8;
            uint32_t ds = so + row * 80 + c8 * 2;
            cpa(ds, d_Ah + ga, pr);
            size_t gb = (size_t)row * NK + k0 + c8;
            cpa(ds + 10240, d_Bh + gb, 16);
        }
    };

    issue(0, 0); CP_COMMIT();
    issue(1, 1); CP_COMMIT();
    for (int ch = 0; ch < KCH; ch++) {
        if (ch + 2 < KCH) issue(ch + 2, (ch + 2) % NSTG);
        CP_COMMIT();
        CP_WAIT2();
        __syncthreads();
        mma_block(sm, ch % NSTG, wm, wn, acc);
        __syncthreads();
    }
    CP_WAIT0();

    float* P = d_P + (size_t)kz * MPAD * 128;
    #pragma unroll
    for (int i = 0; i < 2; i++)
        #pragma unroll
        for (int j = 0; j < 4; j++)
            wmma::store_matrix_sync(&P[(size_t)(m0 + wm + i * 16) * 128 + wn + j * 16],
                                    acc[i][j], 128, wmma::mem_row_major);
}

__global__ void finish_h(const float* __restrict__ bias1) {
    int idx = blockIdx.x * blockDim.x + threadIdx.x;
    if (idx >= NNODES * 32) return;
    int row = idx >> 5, c4 = (idx & 31) << 2;
    size_t o = (size_t)row * 128 + c4;
    float4 a = *(const float4*)&d_P[o];
    float4 b = *(const float4*)&d_P[(size_t)MPAD * 128 + o];
    float4 c = *(const float4*)&d_P[2 * (size_t)MPAD * 128 + o];
    __align__(8) __half hv[4];
    hv[0] = __float2half(a.x + b.x + c.x + bias1[c4]);
    hv[1] = __float2half(a.y + b.y + c.y + bias1[c4 + 1]);
    hv[2] = __float2half(a.z + b.z + c.z + bias1[c4 + 2]);
    hv[3] = __float2half(a.w + b.w + c.w + bias1[c4 + 3]);
    *(uint2*)&d_hh[o] = *(uint2*)hv;
}

__global__ void __launch_bounds__(256, 2) gemm2_wmma() {
    extern __shared__ __align__(16) char sm[];
    uint32_t sa = smem_u32(sm);
    int tid = threadIdx.x, wid = tid >> 5;
    int m0 = blockIdx.x << 7;
    int n0 = blockIdx.y << 7;
    int wm = (wid & 3) << 5;
    int wn = (wid >> 2) << 6;

    FragC acc[2][4];
    #pragma unroll
    for (int i = 0; i < 2; i++)
        #pragma unroll
        for (int j = 0; j < 4; j++) wmma::fill_fragment(acc[i][j], 0.0f);

    auto issue = [&](int ch, int st) {
        int k0 = ch << 5;
        uint32_t so = sa + st * STAGE_B;
        #pragma unroll
        for (int t = tid; t < 512; t += 256) {
            int row = t >> 2, c8 = (t & 3) << 3;
            int gr = m0 + row;
            int pr = (gr < NNODES) ? 16 : 0;
            int grc = (gr < NNODES) ? gr : 0;
            size_t ga = (size_t)grc * 128 + k0 + c8;
            uint32_t ds = so + row * 80 + c8 * 2;
            cpa(ds, d_hh + ga, pr);
            size_t gb = (size_t)(n0 + row) * 128 + k0 + c8;
            cpa(ds + 10240, d_Ch + gb, 16);
        }
    };

    issue(0, 0); CP_COMMIT();
    issue(1, 1); CP_COMMIT();
    for (int ch = 0; ch < 4; ch++) {
        if (ch + 2 < 4) issue(ch + 2, (ch + 2) % NSTG);
        CP_COMMIT();
        CP_WAIT2();
        __syncthreads();
        mma_block(sm, ch % NSTG, wm, wn, acc);
        __syncthreads();
    }
    CP_WAIT0();
    __syncthreads();

    float* sC = (float*)sm;
    #pragma unroll
    for (int i = 0; i < 2; i++)
        #pragma unroll
        for (int j = 0; j < 4; j++)
            wmma::store_matrix_sync(&sC[(wm + i * 16) * 132 + wn + j * 16],
                                    acc[i][j], 132, wmma::mem_row_major);
    __syncthreads();
    int sel = n0 >> 7;
    for (int t = tid; t < 4096; t += 256) {
        int row = t >> 5, c4 = (t & 31) << 2;
        int gr = m0 + row;
        if (gr >= NNODES) continue;
        const float* p = &sC[row * 132 + c4];
        int c = n0 + c4;
        float v0 = p[0] + d_bcat[c],     v1 = p[1] + d_bcat[c + 1];
        float v2 = p[2] + d_bcat[c + 2], v3 = p[3] + d_bcat[c + 3];
        if (sel == 0 || sel == 3) {
            float* dst = &d_kskip[(size_t)gr * 256 + ((sel == 0) ? c4 : 128 + c4)];
            *(float4*)dst = make_float4(v0, v1, v2, v3);
        } else {
            __align__(8) __half hv[4];
            hv[0] = __float2half(v0); hv[1] = __float2half(v1);
            hv[2] = __float2half(v2); hv[3] = __float2half(v3);
            __half* dst = &d_qvh[(size_t)gr * 256 + ((sel == 1) ? c4 : 128 + c4)];
            *(uint2*)dst = *(uint2*)hv;
        }
    }
}

// ---------------- gate: fp32 k/skip, fp16 q/v, tanh.approx sigmoid ----------------
__global__ void gate_kernel(float* __restrict__ out) {
    int dst = blockIdx.x * 8 + (threadIdx.x >> 5);
    if (dst >= NNODES) return;
    int lane = threadIdx.x & 31;
    const float4* ks4 = reinterpret_cast<const float4*>(d_kskip);
    const uint2*  qv2 = reinterpret_cast<const uint2*>(d_qvh);
    float4 kd  = ks4[(size_t)dst * 64 + lane];
    float4 acc = ks4[(size_t)dst * 64 + 32 + lane];
    int beg = d_off[dst * NREL];
    int end = d_off[dst * NREL + NREL];
    for (int e = beg; e < end; e++) {
        int s = d_ssrc[e];
        uint2 qr = __ldg(&qv2[(size_t)s * 64 + lane]);
        uint2 vr = __ldg(&qv2[(size_t)s * 64 + 32 + lane]);
        float2 q01 = __half22float2(*(const __half2*)&qr.x);
        float2 q23 = __half22float2(*(const __half2*)&qr.y);
        float2 v01 = __half22float2(*(const __half2*)&vr.x);
        float2 v23 = __half22float2(*(const __half2*)&vr.y);
        acc.x += v01.x * sigf(kd.x + q01.x);
        acc.y += v01.y * sigf(kd.y + q01.y);
        acc.z += v23.x * sigf(kd.z + q23.x);
        acc.w += v23.y * sigf(kd.w + q23.y);
    }
    reinterpret_cast<float4*>(out)[(size_t)dst * 32 + lane] = acc;
}

// ---------------- launcher ----------------
extern "C" void kernel_launch(void* const* d_in, const int* in_sizes, int n_in,
                              void* d_out, int out_size) {
    const float* x     = (const float*)d_in[0];
    const int*   ei    = (const int*)  d_in[1];
    const int*   etype = (const int*)  d_in[3];
    const float* basis = (const float*)d_in[4];
    const float* comp  = (const float*)d_in[5];
    const float* root  = (const float*)d_in[6];
    const float* bias1 = (const float*)d_in[7];
    const float* wk = (const float*)d_in[8];  const float* bk = (const float*)d_in[9];
    const float* wq = (const float*)d_in[10]; const float* bq = (const float*)d_in[11];
    const float* wv = (const float*)d_in[12]; const float* bv = (const float*)d_in[13];
    const float* ws = (const float*)d_in[14]; const float* bs = (const float*)d_in[15];
    float* out = (float*)d_out;

    cudaFuncSetAttribute(gemm1_wmma, cudaFuncAttributeMaxDynamicSharedMemorySize, GSMEM);
    cudaFuncSetAttribute(gemm2_wmma, cudaFuncAttributeMaxDynamicSharedMemorySize, GSMEM);

    convert_xh<<<(NNODES * 32 + 255) / 256, 256>>>(x);
    prep_weights<<<(128 * NK + 512 * 128 + 255) / 256, 256>>>(comp, basis, root,
                                                              wk, bk, wq, bq, wv, bv, ws, bs);

    count_edges<<<(NEDGES + 255) / 256, 256>>>(ei, etype);
    scan_blocksum<<<NSCAN, SCAN_B>>>();
    scan_partials<<<1, SCAN_B>>>();
    scan_final<<<NSCAN, SCAN_B>>>();
    scatter_edges<<<(NEDGES + 255) / 256, 256>>>(ei, etype);

    agg_all<<<AGG_SEG_BLK + AGG_CPY_BLK, 256>>>();

    gemm1_wmma<<<dim3(MT, KZ), 256, GSMEM>>>();
    finish_h<<<(NNODES * 32 + 511) / 512, 512>>>(bias1);
    gemm2_wmma<<<dim3(MT, 4), 256, GSMEM>>>();

    gate_kernel<<<(NNODES + 7) / 8, 256>>>(out);
}